// round 15
// baseline (speedup 1.0000x reference)
#include <cuda_runtime.h>
#include <math.h>

#define BATCH   128
#define CCH     16
#define TLEN    40000
#define DIMSEL  8
#define TSTART  6000
#define SEGLEN  8064     /* 14064 - 6000 */
#define KS      64
#define NWIN    8001     /* SEGLEN - KS + 1 */
#define EOUT    32
#define NT      288
#define WPT     28       /* base = 28*tid ; f4 base = 7*tid ; gcd(7,8)=1: no skew */

#define NF4     2032     /* max f4 read = 7*287 + 22 = 2031 ; tail [2016,2032) zeroed */

typedef unsigned long long ull;

#define FMA2(d, a, b, c) \
    asm("fma.rn.f32x2 %0, %1, %2, %3;" : "=l"(d) : "l"(a), "l"(b), "l"(c))
#define ADD2(d, a, c) \
    asm("add.rn.f32x2 %0, %1, %2;" : "=l"(d) : "l"(a), "l"(c))
#define PACK2(d, lo, hi) \
    asm("mov.b64 %0, {%1, %2};" : "=l"(d) : "f"(lo), "f"(hi))
#define UNPACK2(lo, hi, s) \
    asm("mov.b64 {%0, %1}, %2;" : "=f"(lo), "=f"(hi) : "l"(s))

__global__ __launch_bounds__(NT, 1)
void shapelet_kernel(const float* __restrict__ x,
                     const float* __restrict__ shp,
                     const float* __restrict__ l1_w,
                     const float* __restrict__ l1_b,
                     const float* __restrict__ l2_w,
                     const float* __restrict__ l2_b,
                     float* __restrict__ out)
{
    __shared__ float4 seg4[NF4];
    __shared__ float2 p2sh[KS];          /* p2sh[k] = (sc[k], sc[k+1]), centered */
    __shared__ float  sc0_sh;
    __shared__ float  redS[NT / 32];
    __shared__ int    redI[NT / 32];

    const int b    = blockIdx.x;
    const int tid  = threadIdx.x;
    const int lane = tid & 31;
    const int wid  = tid >> 5;

    // ---- phase 0: issue seg LDGs first (DRAM latency window opens) ----
    const float* xb = x + ((size_t)b * CCH + DIMSEL) * TLEN + TSTART;
    const float4* xb4 = (const float4*)xb;          /* offset % 4 floats == 0 */
    float4 ld[7];
    #pragma unroll
    for (int u = 0; u < 7; u++)
        ld[u] = xb4[tid + u * NT];                  /* 288*7 = 2016 exactly */

    // ---- shapelet prep under the DRAM wait ----
    if (tid < KS) {
        const float4* s4 = (const float4*)shp;
        float4 a4 = s4[0];
        float sx = a4.x, sy = a4.y, sz = a4.z, sw = a4.w;
        #pragma unroll
        for (int m = 1; m < KS / 4; m++) {
            const float4 t4 = s4[m];
            sx += t4.x; sy += t4.y; sz += t4.z; sw += t4.w;
        }
        const float mean = (sx + sy + sz + sw) * (1.0f / KS);
        const float a = shp[tid] - mean;
        const float c = (tid < KS - 1) ? (shp[tid + 1] - mean) : 0.f;
        p2sh[tid] = make_float2(a, c);
        if (tid == 0) sc0_sh = a;
    }

    // ---- widx-independent half of the head, also under the DRAM wait ----
    float pre = 0.f;                     /* live only in warp 0 */
    if (tid < EOUT) {
        const float4* s4  = (const float4*)shp;
        const float4* w24 = (const float4*)(l2_w + tid * KS);
        float a0 = 0.f, a1 = 0.f, a2 = 0.f, a3 = 0.f;
        #pragma unroll
        for (int m = 0; m < KS / 4; m++) {
            const float4 sv = s4[m];
            const float4 wv = w24[m];
            a0 = fmaf(sv.x, wv.x, a0);
            a1 = fmaf(sv.y, wv.y, a1);
            a2 = fmaf(sv.z, wv.z, a2);
            a3 = fmaf(sv.w, wv.w, a3);
        }
        pre = l1_b[tid] - l2_b[tid] - ((a0 + a1) + (a2 + a3));
    }

    // ---- zero logical tail, store staged seg, ONE barrier ----
    if (tid < NF4 - SEGLEN / 4)                     /* q in [2016, 2032): 16 */
        seg4[SEGLEN / 4 + tid] = make_float4(0.f, 0.f, 0.f, 0.f);
    #pragma unroll
    for (int u = 0; u < 7; u++)
        seg4[tid + u * NT] = ld[u];
    __syncthreads();

    // ---- packed streaming dots: 28 windows/thread, batched LDS.128 ----
    const int tb = tid * 7;              /* f4 base; window base = tid*28 */
    ull dot2[WPT];
    #pragma unroll
    for (int i = 0; i < WPT; i++) dot2[i] = 0ull;
    ull sum2 = 0ull, sq2 = 0ull;

    #pragma unroll
    for (int c = 0; c < 4; c++) {        /* shapelet scalars k in [16c, 16c+16) */
        ull p2r[16];
        #pragma unroll
        for (int n = 0; n < 16; n++)
            p2r[n] = *(const ull*)&p2sh[16 * c + n];  /* broadcast LDS.64 */

        /* m in [4c, 4c+11): 3 batches of (4,4,3) */
        #pragma unroll
        for (int bq = 0; bq < 3; bq++) {
            const int bsz = (bq == 2) ? 3 : 4;
            float4 Fh[4];
            #pragma unroll
            for (int q = 0; q < 4; q++)
                if (q < bsz) Fh[q] = seg4[tb + 4 * c + 4 * bq + q];  /* MLP=4 */

            #pragma unroll
            for (int q = 0; q < 4; q++) {
                if (q >= bsz) continue;
                const int m  = 4 * c + 4 * bq + q;
                const float4 F = Fh[q];
                ull vp0, vp1;
                PACK2(vp0, F.x, F.y);    /* scalars j = 4m, 4m+1   */
                PACK2(vp1, F.z, F.w);    /* scalars j = 4m+2, 4m+3 */

                /* window-0 sum/sumsq: count each m in [0,16) exactly once */
                if (((c == 0) ||
                     (c == 1 && m >= 11) ||
                     (c == 2 && m == 15)) && (m < 16)) {
                    ADD2(sum2, vp0, sum2);  FMA2(sq2, vp0, vp0, sq2);
                    ADD2(sum2, vp1, sum2);  FMA2(sq2, vp1, vp1, sq2);
                }

                #pragma unroll
                for (int i = 0; i < WPT; i++) {
                    const int k0 = 4 * m - i;             /* compile-time */
                    if (k0 >= 16 * c && k0 < 16 * c + 16)
                        FMA2(dot2[i], vp0, p2r[k0 - 16 * c], dot2[i]);
                    const int k1 = 4 * m + 2 - i;
                    if (k1 >= 16 * c && k1 < 16 * c + 16)
                        FMA2(dot2[i], vp1, p2r[k1 - 16 * c], dot2[i]);
                }
            }
        }
    }

    // ---- scores: window 0, then 7 groups of 4 windows fed by 2 LDS.128 ----
    const int base = tid * WPT;
    float sum, sq;
    {
        float a, bb;
        UNPACK2(a, bb, sum2); sum = a + bb;
        UNPACK2(a, bb, sq2);  sq  = a + bb;
    }
    float best;
    int   bidx;
    {
        float dlo, dhi;
        UNPACK2(dlo, dhi, dot2[0]);
        const float den = sq - sum * sum * (1.0f / KS);
        best = (dlo + dhi) * rsqrtf(den);
        bidx = base;
        if (base >= NWIN) { best = -INFINITY; bidx = NWIN; }
    }
    ull edge; PACK2(edge, 0.0f, sc0_sh);

    #pragma unroll
    for (int g = 0; g < 7; g++) {
        const float4 Fo = seg4[tb + g];              /* e = base+4g .. +3    */
        const float4 Fn = seg4[tb + 16 + g];         /* e = base+64+4g .. +3 */

        /* odd-window leading edge: i = 4g+1 (Fo.xy), i = 4g+3 (Fo.zw) */
        ull vp;
        PACK2(vp, Fo.x, Fo.y); FMA2(dot2[4 * g + 1], vp, edge, dot2[4 * g + 1]);
        PACK2(vp, Fo.z, Fo.w); FMA2(dot2[4 * g + 3], vp, edge, dot2[4 * g + 3]);

        const float ov[4] = {Fo.x, Fo.y, Fo.z, Fo.w};
        const float nv[4] = {Fn.x, Fn.y, Fn.z, Fn.w};
        #pragma unroll
        for (int t = 0; t < 4; t++) {
            const int i = 4 * g + 1 + t;
            if (i >= WPT) continue;                  /* g=6, t=3 */
            const float vo = ov[t];
            const float vn = nv[t];
            sum += vn - vo;
            sq  += fmaf(vn, vn, -vo * vo);
            float dlo, dhi;
            UNPACK2(dlo, dhi, dot2[i]);
            const float den = sq - sum * sum * (1.0f / KS);
            const float scv = (dlo + dhi) * rsqrtf(den);  /* NaN on pad: guarded */
            const int   w   = base + i;
            if (w < NWIN && scv > best) { best = scv; bidx = w; }  /* strict > */
        }
    }

    // ---- argmax: warp shfl; then all warps except 0 retire ----
    #pragma unroll
    for (int off = 16; off > 0; off >>= 1) {
        const float so = __shfl_xor_sync(0xffffffffu, best, off);
        const int   io = __shfl_xor_sync(0xffffffffu, bidx, off);
        if (so > best || (so == best && io < bidx)) { best = so; bidx = io; }
    }
    if (lane == 0) { redS[wid] = best; redI[wid] = bidx; }
    __syncthreads();
    if (wid != 0) return;                /* no further barriers: safe early exit */

    best = (lane < NT / 32) ? redS[lane] : -INFINITY;
    bidx = (lane < NT / 32) ? redI[lane] : NWIN;
    #pragma unroll
    for (int off = 16; off > 0; off >>= 1) {
        const float so = __shfl_xor_sync(0xffffffffu, best, off);
        const int   io = __shfl_xor_sync(0xffffffffu, bidx, off);
        if (so > best || (so == best && io < bidx)) { best = so; bidx = io; }
    }
    const int widx = bidx;               /* bfly: every lane holds the winner */

    // ---- head: widx-dependent half only (plain layout: direct indexing) ----
    {
        const float* segf = (const float*)seg4;
        const float4* w14 = (const float4*)(l1_w + tid * KS);
        float a0 = 0.f, a1 = 0.f, a2 = 0.f, a3 = 0.f;
        #pragma unroll
        for (int m = 0; m < KS / 4; m++) {
            const float4 wv = w14[m];
            const float* sp = segf + widx + 4 * m;
            a0 = fmaf(sp[0], wv.x, a0);
            a1 = fmaf(sp[1], wv.y, a1);
            a2 = fmaf(sp[2], wv.z, a2);
            a3 = fmaf(sp[3], wv.w, a3);
        }
        out[b * EOUT + tid] = pre + ((a0 + a1) + (a2 + a3));
    }
}

extern "C" void kernel_launch(void* const* d_in, const int* in_sizes, int n_in,
                              void* d_out, int out_size)
{
    const float* x    = (const float*)d_in[0];
    const float* shp  = (const float*)d_in[1];
    const float* l1_w = (const float*)d_in[2];
    const float* l1_b = (const float*)d_in[3];
    const float* l2_w = (const float*)d_in[4];
    const float* l2_b = (const float*)d_in[5];
    float* out = (float*)d_out;

    shapelet_kernel<<<BATCH, NT>>>(x, shp, l1_w, l1_b, l2_w, l2_b, out);
}

// round 16
// speedup vs baseline: 1.1940x; 1.1940x over previous
#include <cuda_runtime.h>
#include <math.h>

#define BATCH   128
#define CCH     16
#define TLEN    40000
#define DIMSEL  8
#define TSTART  6000
#define SEGLEN  8064     /* 14064 - 6000 */
#define KS      64
#define NWIN    8001     /* SEGLEN - KS + 1 */
#define EOUT    32
#define NT      256
#define WPT     32       /* base = 32*tid ; f4 base = 8*tid ; reg budget 255 */

#define NF4     2064     /* logical f4 count; max q read = 8*255+19 = 2059 */
#define SKEW(q) ((q) + ((q) >> 3))          /* stride-8 reads -> bank (l+m)%8 : clean */
#define SEGF4   (SKEW(NF4 - 1) + 1)         /* 2321 f4 = 37.1 KB */

typedef unsigned long long ull;

#define FMA2(d, a, b, c) \
    asm("fma.rn.f32x2 %0, %1, %2, %3;" : "=l"(d) : "l"(a), "l"(b), "l"(c))
#define ADD2(d, a, c) \
    asm("add.rn.f32x2 %0, %1, %2;" : "=l"(d) : "l"(a), "l"(c))
#define PACK2(d, lo, hi) \
    asm("mov.b64 %0, {%1, %2};" : "=l"(d) : "f"(lo), "f"(hi))
#define UNPACK2(lo, hi, s) \
    asm("mov.b64 {%0, %1}, %2;" : "=f"(lo), "=f"(hi) : "l"(s))

__global__ __launch_bounds__(NT, 1)
void shapelet_kernel(const float* __restrict__ x,
                     const float* __restrict__ shp,
                     const float* __restrict__ l1_w,
                     const float* __restrict__ l1_b,
                     const float* __restrict__ l2_w,
                     const float* __restrict__ l2_b,
                     float* __restrict__ out)
{
    __shared__ float4 seg4[SEGF4];
    __shared__ float2 p2sh[KS];          /* p2sh[k] = (sc[k], sc[k+1]), centered */
    __shared__ float  sc0_sh;
    __shared__ float  redS[NT / 32];
    __shared__ int    redI[NT / 32];

    const int b    = blockIdx.x;
    const int tid  = threadIdx.x;
    const int lane = tid & 31;
    const int wid  = tid >> 5;

    // ---- phase 0: issue seg LDGs first (DRAM latency window opens) ----
    const float* xb = x + ((size_t)b * CCH + DIMSEL) * TLEN + TSTART;
    const float4* xb4 = (const float4*)xb;          /* offset % 4 floats == 0 */
    float4 ld[8];
    #pragma unroll
    for (int u = 0; u < 8; u++) {
        const int i = tid + u * NT;
        if (i < SEGLEN / 4) ld[u] = xb4[i];         /* 2016 f4 */
    }

    // ---- shapelet prep under the DRAM wait ----
    if (tid < KS) {
        const float4* s4 = (const float4*)shp;
        float4 a4 = s4[0];
        float sx = a4.x, sy = a4.y, sz = a4.z, sw = a4.w;
        #pragma unroll
        for (int m = 1; m < KS / 4; m++) {
            const float4 t4 = s4[m];
            sx += t4.x; sy += t4.y; sz += t4.z; sw += t4.w;
        }
        const float mean = (sx + sy + sz + sw) * (1.0f / KS);
        const float a = shp[tid] - mean;
        const float c = (tid < KS - 1) ? (shp[tid + 1] - mean) : 0.f;
        p2sh[tid] = make_float2(a, c);
        if (tid == 0) sc0_sh = a;
    }

    // ---- widx-independent half of the head, also under the DRAM wait ----
    float pre = 0.f;                     /* live only in warp 0 */
    if (tid < EOUT) {
        const float4* s4  = (const float4*)shp;
        const float4* w24 = (const float4*)(l2_w + tid * KS);
        float a0 = 0.f, a1 = 0.f, a2 = 0.f, a3 = 0.f;
        #pragma unroll
        for (int m = 0; m < KS / 4; m++) {
            const float4 sv = s4[m];
            const float4 wv = w24[m];
            a0 = fmaf(sv.x, wv.x, a0);
            a1 = fmaf(sv.y, wv.y, a1);
            a2 = fmaf(sv.z, wv.z, a2);
            a3 = fmaf(sv.w, wv.w, a3);
        }
        pre = l1_b[tid] - l2_b[tid] - ((a0 + a1) + (a2 + a3));
    }

    // ---- zero logical tail, store staged seg, ONE barrier ----
    if (tid < NF4 - SEGLEN / 4)                     /* q in [2016, 2064): 48 */
        seg4[SKEW(SEGLEN / 4 + tid)] = make_float4(0.f, 0.f, 0.f, 0.f);
    #pragma unroll
    for (int u = 0; u < 8; u++) {
        const int i = tid + u * NT;
        if (i < SEGLEN / 4) seg4[SKEW(i)] = ld[u];
    }
    __syncthreads();

    // ---- packed streaming dots: 32 windows/thread, 2 chunks of 32 scalars ----
    const int tb = tid * 8;              /* f4 base; window base = tid*32 */
    ull dot2[WPT];
    #pragma unroll
    for (int i = 0; i < WPT; i++) dot2[i] = 0ull;
    ull sum2 = 0ull, sq2 = 0ull;

    #pragma unroll
    for (int c = 0; c < 2; c++) {        /* shapelet scalars k in [32c, 32c+32) */
        ull p2r[32];
        #pragma unroll
        for (int n = 0; n < 32; n++)
            p2r[n] = *(const ull*)&p2sh[32 * c + n];  /* broadcast LDS.64 */

        #pragma unroll
        for (int bq = 0; bq < 4; bq++) { /* f4 m = 8c + 4bq + q, m in [8c, 8c+16) */
            float4 Fh[4];
            #pragma unroll
            for (int q = 0; q < 4; q++)
                Fh[q] = seg4[SKEW(tb + 8 * c + 4 * bq + q)];   /* MLP = 4 */

            #pragma unroll
            for (int q = 0; q < 4; q++) {
                const int m = 8 * c + 4 * bq + q;
                const float4 F = Fh[q];
                ull vp0, vp1;
                PACK2(vp0, F.x, F.y);    /* scalars j = 4m, 4m+1   */
                PACK2(vp1, F.z, F.w);    /* scalars j = 4m+2, 4m+3 */

                /* window-0 sum/sumsq: chunk 0 covers m in [0,16) exactly */
                if (c == 0) {
                    ADD2(sum2, vp0, sum2);  FMA2(sq2, vp0, vp0, sq2);
                    ADD2(sum2, vp1, sum2);  FMA2(sq2, vp1, vp1, sq2);
                }

                #pragma unroll
                for (int i = 0; i < WPT; i++) {
                    const int k0 = 4 * m - i;             /* compile-time */
                    if (k0 >= 32 * c && k0 < 32 * c + 32)
                        FMA2(dot2[i], vp0, p2r[k0 - 32 * c], dot2[i]);
                    const int k1 = 4 * m + 2 - i;
                    if (k1 >= 32 * c && k1 < 32 * c + 32)
                        FMA2(dot2[i], vp1, p2r[k1 - 32 * c], dot2[i]);
                }
            }
        }
    }

    // ---- scores: window 0, then 8 groups of 4 windows fed by 2 LDS.128 ----
    const int base = tid * WPT;
    float sum, sq;
    {
        float a, bb;
        UNPACK2(a, bb, sum2); sum = a + bb;
        UNPACK2(a, bb, sq2);  sq  = a + bb;
    }
    float best;
    int   bidx;
    {
        float dlo, dhi;
        UNPACK2(dlo, dhi, dot2[0]);
        const float den = sq - sum * sum * (1.0f / KS);
        best = (dlo + dhi) * rsqrtf(den);
        bidx = base;
        if (base >= NWIN) { best = -INFINITY; bidx = NWIN; }
    }
    ull edge; PACK2(edge, 0.0f, sc0_sh);

    #pragma unroll
    for (int g = 0; g < 8; g++) {
        const float4 Fo = seg4[SKEW(tb + g)];        /* e = base+4g .. +3    */
        const float4 Fn = seg4[SKEW(tb + 16 + g)];   /* e = base+64+4g .. +3 */

        /* odd-window leading edge: i = 4g+1 (Fo.xy), i = 4g+3 (Fo.zw) */
        ull vp;
        PACK2(vp, Fo.x, Fo.y); FMA2(dot2[4 * g + 1], vp, edge, dot2[4 * g + 1]);
        PACK2(vp, Fo.z, Fo.w); FMA2(dot2[4 * g + 3], vp, edge, dot2[4 * g + 3]);

        const float ov[4] = {Fo.x, Fo.y, Fo.z, Fo.w};
        const float nv[4] = {Fn.x, Fn.y, Fn.z, Fn.w};
        #pragma unroll
        for (int t = 0; t < 4; t++) {
            const int i = 4 * g + 1 + t;
            if (i >= WPT) continue;                  /* g=7, t=3 */
            const float vo = ov[t];
            const float vn = nv[t];
            sum += vn - vo;
            sq  += fmaf(vn, vn, -vo * vo);
            float dlo, dhi;
            UNPACK2(dlo, dhi, dot2[i]);
            const float den = sq - sum * sum * (1.0f / KS);
            const float scv = (dlo + dhi) * rsqrtf(den);  /* NaN on pad: guarded */
            const int   w   = base + i;
            if (w < NWIN && scv > best) { best = scv; bidx = w; }  /* strict > */
        }
    }

    // ---- argmax: warp shfl; then all warps except 0 retire ----
    #pragma unroll
    for (int off = 16; off > 0; off >>= 1) {
        const float so = __shfl_xor_sync(0xffffffffu, best, off);
        const int   io = __shfl_xor_sync(0xffffffffu, bidx, off);
        if (so > best || (so == best && io < bidx)) { best = so; bidx = io; }
    }
    if (lane == 0) { redS[wid] = best; redI[wid] = bidx; }
    __syncthreads();
    if (wid != 0) return;                /* no further barriers: safe early exit */

    best = (lane < NT / 32) ? redS[lane] : -INFINITY;
    bidx = (lane < NT / 32) ? redI[lane] : NWIN;
    #pragma unroll
    for (int off = 16; off > 0; off >>= 1) {
        const float so = __shfl_xor_sync(0xffffffffu, best, off);
        const int   io = __shfl_xor_sync(0xffffffffu, bidx, off);
        if (so > best || (so == best && io < bidx)) { best = so; bidx = io; }
    }
    const int widx = bidx;               /* bfly: every lane holds the winner */

    // ---- head: widx-dependent half only ----
    {
        const float* segf = (const float*)seg4;
        const float4* w14 = (const float4*)(l1_w + tid * KS);
        float a0 = 0.f, a1 = 0.f, a2 = 0.f, a3 = 0.f;
        #pragma unroll
        for (int m = 0; m < KS / 4; m++) {
            const float4 wv = w14[m];
            const int e = widx + 4 * m;
            a0 = fmaf(segf[SKEW((e + 0) >> 2) * 4 + ((e + 0) & 3)], wv.x, a0);
            a1 = fmaf(segf[SKEW((e + 1) >> 2) * 4 + ((e + 1) & 3)], wv.y, a1);
            a2 = fmaf(segf[SKEW((e + 2) >> 2) * 4 + ((e + 2) & 3)], wv.z, a2);
            a3 = fmaf(segf[SKEW((e + 3) >> 2) * 4 + ((e + 3) & 3)], wv.w, a3);
        }
        out[b * EOUT + tid] = pre + ((a0 + a1) + (a2 + a3));
    }
}

extern "C" void kernel_launch(void* const* d_in, const int* in_sizes, int n_in,
                              void* d_out, int out_size)
{
    const float* x    = (const float*)d_in[0];
    const float* shp  = (const float*)d_in[1];
    const float* l1_w = (const float*)d_in[2];
    const float* l1_b = (const float*)d_in[3];
    const float* l2_w = (const float*)d_in[4];
    const float* l2_b = (const float*)d_in[5];
    float* out = (float*)d_out;

    shapelet_kernel<<<BATCH, NT>>>(x, shp, l1_w, l1_b, l2_w, l2_b, out);
}